// round 3
// baseline (speedup 1.0000x reference)
#include <cuda_runtime.h>
#include <cuda_bf16.h>

// Output: [B=64, 4, 256, 256, 3] f32; scales sorted: 32,64,128,256.
// One block per output row, 192 threads (one float4 of the 768-float row each).
// Resize rows: stage src rows y0/y1 in smem (coalesced), interp one thread per
// output-row float into smem, then coalesced float4 store with uniform padding.

#define HW    256
#define ROWF  (HW * 3)     // 768 floats per row
#define ROW4  (ROWF / 4)   // 192 float4 per row

__global__ void __launch_bounds__(192)
msp_kernel(const float* __restrict__ in, float4* __restrict__ out4)
{
    __shared__ float s_r0[ROWF];
    __shared__ float s_r1[ROWF];
    __shared__ float s_out[3 * 128];   // widest interior row: 3*s, s<=128

    const int t  = threadIdx.x;        // 0..191
    const int y  = blockIdx.x;         // 0..255
    const int si = blockIdx.y;         // 0..3
    const int b  = blockIdx.z;         // 0..63

    const long long oi = (((long long)(b * 4 + si) * HW + y) * ROW4) + t;

    if (si == 3) {
        // Native 256x256 pass-through: coalesced float4 copy.
        out4[oi] = ((const float4*)in)[(b * HW + y) * ROW4 + t];
        return;
    }

    const int s = 32 << si;            // 32, 64, 128
    const int p = (HW - s) >> 1;       // centered pad

    if (y < p || y >= p + s) {
        out4[oi] = make_float4(0.f, 0.f, 0.f, 0.f);   // pure pad row
        return;
    }

    const float r  = 255.0f / (float)(s - 1);
    const float fy = (float)(y - p) * r;
    int   y0 = (int)fy;           if (y0 > 255) y0 = 255;
    int   y1 = min(y0 + 1, 255);
    const float wy  = fy - (float)y0;
    const float omy = 1.0f - wy;

    // Stage the two source rows: 1 coalesced float4 load per thread per row.
    ((float4*)s_r0)[t] = ((const float4*)(in + (b * HW + y0) * ROWF))[t];
    ((float4*)s_r1)[t] = ((const float4*)(in + (b * HW + y1) * ROWF))[t];
    __syncthreads();

    // Phase A: one thread per interior-row float (3*s total, <=384).
    const int W = 3 * s;
    for (int j = t; j < W; j += 192) {
        const int x = (int)((unsigned)j / 3u);   // interior pixel 0..s-1
        const int c = j - x * 3;
        const float fx = (float)x * r;
        int   x0 = (int)fx;       if (x0 > 255) x0 = 255;
        int   x1 = min(x0 + 1, 255);
        const float wx  = fx - (float)x0;
        const float omw = 1.0f - wx;
        const float top = s_r0[x0 * 3 + c] * omw + s_r0[x1 * 3 + c] * wx;
        const float bot = s_r1[x0 * 3 + c] * omw + s_r1[x1 * 3 + c] * wx;
        s_out[j] = top * omy + bot * wy;
    }
    __syncthreads();

    // Phase B: coalesced float4 store. 3p and 3s divisible by 4, so each
    // float4 slot is entirely pad or entirely interior.
    const int lo = (3 * p) >> 2;
    const int hi = lo + (W >> 2);
    float4 v = make_float4(0.f, 0.f, 0.f, 0.f);
    if (t >= lo && t < hi) v = ((const float4*)s_out)[t - lo];
    out4[oi] = v;
}

extern "C" void kernel_launch(void* const* d_in, const int* in_sizes, int n_in,
                              void* d_out, int out_size)
{
    const float* images = (const float*)d_in[0];
    float4* out4 = (float4*)d_out;

    dim3 grid(HW, 4, 64);   // y, scale-index, batch
    dim3 block(192);
    msp_kernel<<<grid, block>>>(images, out4);
}